// round 4
// baseline (speedup 1.0000x reference)
#include <cuda_runtime.h>
#include <cuda_bf16.h>
#include <cstdint>

#define N0 50000
#define N1 150000
#define N2 20000
#define N3 5000
#define N4 1000
#define E0 800000
#define E1 1500000
#define NNZ01 300000
#define DIM 64

#define N0D (N0*DIM)
#define N1D (N1*DIM)

#define ET   (E0 + E1 + 2*NNZ01)     // 2,900,000
#define NCNT (2*(N0 + N1))           // 400,000
#define B0 0
#define B1 (N0)
#define B2 (N0+N1)
#define B3 (N0+N1+N0)

#define SCAN_BLK 1024
#define NB ((NCNT + SCAN_BLK - 1)/SCAN_BLK)   // 391

// -------------------------- device scratch ---------------------------------
__device__ float g_m[2*(N0D + N1D)];        // [m0 | mt | m1 | ms]
__device__ float g_sum[N0D + N1D];
__device__ float g_coef[E0 + E1];
__device__ int   g_cnt[NCNT];
__device__ int   g_offs[NCNT + 1];
__device__ int   g_bsums[NB + 1];
__device__ int2  g_rec[ET];

// ---------------------------------------------------------------------------
// shared GEMM tile routine: outA = x@WA, outB = x@WB (32-row tiles, 128 thr)
__device__ __forceinline__ void gemm_dual_body(
    const float* __restrict__ x, const float* __restrict__ WA, const float* __restrict__ WB,
    float* __restrict__ outA, float* __restrict__ outB, int nrows,
    int bid, int nblocks,
    float* sWA, float* sWB, float (*sXT)[36])
{
    int tid = threadIdx.x;
    for (int i = tid*4; i < 4096; i += 128*4) {
        *(float4*)&sWA[i] = *(const float4*)&WA[i];
        *(float4*)&sWB[i] = *(const float4*)&WB[i];
    }
    int ntiles = (nrows + 31) >> 5;
    int tx = tid & 15;
    int ty = tid >> 4;

    for (int tile = bid; tile < ntiles; tile += nblocks) {
        int row0 = tile << 5;
        __syncthreads();
        #pragma unroll
        for (int i = 0; i < 4; i++) {
            int q  = tid + i*128;
            int r  = q >> 4;
            int c4 = (q & 15) << 2;
            float4 v = make_float4(0.f,0.f,0.f,0.f);
            if (row0 + r < nrows) v = *(const float4*)&x[(size_t)(row0 + r)*DIM + c4];
            sXT[c4+0][r] = v.x; sXT[c4+1][r] = v.y; sXT[c4+2][r] = v.z; sXT[c4+3][r] = v.w;
        }
        __syncthreads();

        float aA[4][4] = {}; float aB[4][4] = {};
        #pragma unroll
        for (int k = 0; k < 64; k++) {
            float4 xv = *(float4*)&sXT[k][ty*4];
            float4 wa = *(float4*)&sWA[k*64 + tx*4];
            float4 wb = *(float4*)&sWB[k*64 + tx*4];
            float xr[4]  = {xv.x, xv.y, xv.z, xv.w};
            float wac[4] = {wa.x, wa.y, wa.z, wa.w};
            float wbc[4] = {wb.x, wb.y, wb.z, wb.w};
            #pragma unroll
            for (int r = 0; r < 4; r++)
                #pragma unroll
                for (int c = 0; c < 4; c++) {
                    aA[r][c] += xr[r]*wac[c];
                    aB[r][c] += xr[r]*wbc[c];
                }
        }
        #pragma unroll
        for (int r = 0; r < 4; r++) {
            int row = row0 + ty*4 + r;
            if (row < nrows) {
                *(float4*)&outA[(size_t)row*DIM + tx*4] =
                    make_float4(aA[r][0], aA[r][1], aA[r][2], aA[r][3]);
                *(float4*)&outB[(size_t)row*DIM + tx*4] =
                    make_float4(aB[r][0], aB[r][1], aB[r][2], aB[r][3]);
            }
        }
    }
}

// ---------------------------------------------------------------------------
// Phase A: [0,gemmB) -> dual GEMM on x0;  [gemmB, grid) -> coef + count
__global__ void __launch_bounds__(128) phaseA_kernel(
    const float* __restrict__ x0, const float* __restrict__ WA, const float* __restrict__ WB,
    float* __restrict__ outA, float* __restrict__ outB,
    const int* __restrict__ adj0, const int* __restrict__ adj1, const int* __restrict__ inc,
    const float* __restrict__ val0, const float* __restrict__ cci0, const float* __restrict__ a0,
    const float* __restrict__ val1, const float* __restrict__ cci1, const float* __restrict__ a1,
    int gemmB)
{
    __shared__ float sWA[64*64];
    __shared__ float sWB[64*64];
    __shared__ float sXT[64][36];

    if (blockIdx.x < gemmB) {
        gemm_dual_body(x0, WA, WB, outA, outB, N0, blockIdx.x, gemmB, sWA, sWB, sXT);
        return;
    }
    // edge side: coef + histogram
    int nb = gridDim.x - gemmB;
    int stride = nb * 128;
    float a00 = a0[0], a01 = a0[1], a02 = a0[2];
    float a10 = a1[0], a11 = a1[1], a12 = a1[2];
    for (int t = (blockIdx.x - gemmB)*128 + threadIdx.x; t < ET; t += stride) {
        int ci;
        if (t < E0) {
            ci = B0 + __ldg(&adj0[E0 + t]);
            const float* c = cci0 + (size_t)t*3;
            g_coef[t] = __ldg(&val0[t]) * (c[0]*a00 + c[1]*a01 + c[2]*a02);
        } else if (t < E0 + E1) {
            int f = t - E0;
            ci = B1 + __ldg(&adj1[E1 + f]);
            const float* c = cci1 + (size_t)f*3;
            g_coef[E0 + f] = __ldg(&val1[f]) * (c[0]*a10 + c[1]*a11 + c[2]*a12);
        } else if (t < E0 + E1 + NNZ01) {
            ci = B2 + __ldg(&inc[t - (E0 + E1)]);
        } else {
            ci = B3 + __ldg(&inc[NNZ01 + (t - (E0+E1+NNZ01))]);
        }
        atomicAdd(&g_cnt[ci], 1);
    }
}

// ---------------------------------------------------------------------------
// scans (unchanged logic)
__global__ void scan_pass1() {
    __shared__ int wsum[8];
    int tid = threadIdx.x, lane = tid & 31, wid = tid >> 5;
    int base = blockIdx.x * SCAN_BLK + tid * 4;
    int4 v = make_int4(0,0,0,0);
    if (base < NCNT) v = *(const int4*)&g_cnt[base];
    int s = v.x + v.y + v.z + v.w;
    #pragma unroll
    for (int o = 16; o; o >>= 1) s += __shfl_down_sync(0xffffffffu, s, o);
    if (lane == 0) wsum[wid] = s;
    __syncthreads();
    if (tid == 0) {
        int tot = 0;
        #pragma unroll
        for (int i = 0; i < 8; i++) tot += wsum[i];
        g_bsums[blockIdx.x] = tot;
    }
}

__global__ void scan_pass2() {
    __shared__ int sm[512];
    int t = threadIdx.x;
    int v = (t < NB) ? g_bsums[t] : 0;
    sm[t] = v;
    __syncthreads();
    #pragma unroll
    for (int o = 1; o < 512; o <<= 1) {
        int add = (t >= o) ? sm[t - o] : 0;
        __syncthreads();
        sm[t] += add;
        __syncthreads();
    }
    if (t < NB) g_bsums[t] = sm[t] - v;
    if (t == 0) g_offs[NCNT] = ET;
}

__global__ void scan_pass3() {
    __shared__ int woff[8];
    int tid = threadIdx.x, lane = tid & 31, wid = tid >> 5;
    int base = blockIdx.x * SCAN_BLK + tid * 4;
    int4 v = make_int4(0,0,0,0);
    if (base < NCNT) v = *(const int4*)&g_cnt[base];
    int s = v.x + v.y + v.z + v.w;
    int incl = s;
    #pragma unroll
    for (int o = 1; o < 32; o <<= 1) {
        int n = __shfl_up_sync(0xffffffffu, incl, o);
        if (lane >= o) incl += n;
    }
    if (lane == 31) woff[wid] = incl;
    __syncthreads();
    if (tid == 0) {
        int acc = 0;
        #pragma unroll
        for (int i = 0; i < 8; i++) { int t2 = woff[i]; woff[i] = acc; acc += t2; }
    }
    __syncthreads();
    int excl = incl - s + woff[wid] + g_bsums[blockIdx.x];
    if (base < NCNT) {
        g_offs[base]     = excl;
        g_offs[base + 1] = excl + v.x;
        g_offs[base + 2] = excl + v.x + v.y;
        g_offs[base + 3] = excl + v.x + v.y + v.z;
    }
}

// ---------------------------------------------------------------------------
// Phase C: [0,gemmB) -> dual GEMM on x1;  [gemmB, grid) -> fill records
// Position via atomicSub on g_cnt (scan already consumed counts read-only).
__global__ void __launch_bounds__(128) phaseC_kernel(
    const float* __restrict__ x1, const float* __restrict__ WA, const float* __restrict__ WB,
    float* __restrict__ outA, float* __restrict__ outB,
    const int* __restrict__ adj0, const int* __restrict__ adj1,
    const int* __restrict__ inc, const float* __restrict__ incv,
    int gemmB)
{
    __shared__ float sWA[64*64];
    __shared__ float sWB[64*64];
    __shared__ float sXT[64][36];

    if (blockIdx.x < gemmB) {
        gemm_dual_body(x1, WA, WB, outA, outB, N1, blockIdx.x, gemmB, sWA, sWB, sXT);
        return;
    }
    int nb = gridDim.x - gemmB;
    int stride = nb * 128;
    for (int t = (blockIdx.x - gemmB)*128 + threadIdx.x; t < ET; t += stride) {
        int ci, src; float coef;
        if (t < E0) {
            ci   = B0 + __ldg(&adj0[E0 + t]);
            src  = __ldg(&adj0[t]);
            coef = g_coef[t];
        } else if (t < E0 + E1) {
            int f = t - E0;
            ci   = B1 + __ldg(&adj1[E1 + f]);
            src  = __ldg(&adj1[f]);
            coef = g_coef[E0 + f];
        } else if (t < E0 + E1 + NNZ01) {
            int f = t - (E0 + E1);
            ci   = B2 + __ldg(&inc[f]);
            src  = __ldg(&inc[NNZ01 + f]);
            coef = __ldg(&incv[f]);
        } else {
            int f = t - (E0 + E1 + NNZ01);
            ci   = B3 + __ldg(&inc[NNZ01 + f]);
            src  = __ldg(&inc[f]);
            coef = __ldg(&incv[f]);
        }
        int pos = g_offs[ci] + (atomicSub(&g_cnt[ci], 1) - 1);
        g_rec[pos] = make_int2(src, __float_as_int(coef));
    }
}

// ---------------------------------------------------------------------------
// Combined gather: warp per node (both node families in one launch).
// Half-warp per edge: lanes 0-15 edge j, lanes 16-31 edge j+1; each lane
// owns 4 columns (float4). Final shfl_xor(16) combines the two halves.
__device__ __forceinline__ float4 seg_accum4(const float* __restrict__ m,
                                             int s, int e, int lane,
                                             int half, int col4) {
    float4 acc = make_float4(0.f, 0.f, 0.f, 0.f);
    for (int base = s; base < e; base += 32) {
        int idx = base + lane;
        int2 rv = (idx < e) ? __ldg(&g_rec[idx]) : make_int2(0, 0);
        int cnt = min(32, e - base);
        #pragma unroll 2
        for (int j = 0; j < cnt; j += 2) {
            int  has2 = (j + 1 < cnt);
            int  sel  = j + (half & has2);
            int   src = __shfl_sync(0xffffffffu, rv.x, sel);
            float c   = __int_as_float(__shfl_sync(0xffffffffu, rv.y, sel));
            if (half && !has2) c = 0.f;
            float4 v = *(const float4*)&m[(size_t)src*DIM + col4];
            acc.x += c*v.x; acc.y += c*v.y; acc.z += c*v.z; acc.w += c*v.w;
        }
    }
    return acc;
}

__global__ void __launch_bounds__(256) gather_kernel(
    const float* __restrict__ pm0, const float* __restrict__ pms,
    const float* __restrict__ pm1, const float* __restrict__ pmt,
    float* __restrict__ sum0, float* __restrict__ sum1)
{
    int w    = (blockIdx.x * blockDim.x + threadIdx.x) >> 5;
    int lane = threadIdx.x & 31;
    if (w >= N0 + N1) return;
    int half = lane >> 4;
    int col4 = (lane & 15) << 2;

    const float *mA, *mB; float* outp; int node, baseA, baseB;
    if (w < N0) { node = w;      mA = pm0; baseA = B0; mB = pms; baseB = B2; outp = sum0; }
    else        { node = w - N0; mA = pm1; baseA = B1; mB = pmt; baseB = B3; outp = sum1; }

    int sA = g_offs[baseA + node], eA = g_offs[baseA + node + 1];
    int sB = g_offs[baseB + node], eB = g_offs[baseB + node + 1];
    float4 a = seg_accum4(mA, sA, eA, lane, half, col4);
    float4 b = seg_accum4(mB, sB, eB, lane, half, col4);

    // combine halves
    a.x += __shfl_xor_sync(0xffffffffu, a.x, 16);
    a.y += __shfl_xor_sync(0xffffffffu, a.y, 16);
    a.z += __shfl_xor_sync(0xffffffffu, a.z, 16);
    a.w += __shfl_xor_sync(0xffffffffu, a.w, 16);
    b.x += __shfl_xor_sync(0xffffffffu, b.x, 16);
    b.y += __shfl_xor_sync(0xffffffffu, b.y, 16);
    b.z += __shfl_xor_sync(0xffffffffu, b.z, 16);
    b.w += __shfl_xor_sync(0xffffffffu, b.w, 16);

    if (half == 0) {
        float4 r;
        r.x = fmaxf(a.x, 0.f) + fmaxf(b.x, 0.f);
        r.y = fmaxf(a.y, 0.f) + fmaxf(b.y, 0.f);
        r.z = fmaxf(a.z, 0.f) + fmaxf(b.z, 0.f);
        r.w = fmaxf(a.w, 0.f) + fmaxf(b.w, 0.f);
        *(float4*)&outp[(size_t)node*DIM + col4] = r;
    }
}

// ---------------------------------------------------------------------------
// Merged epilogue: out = relu(in @ W) for both regions in one launch.
__global__ void __launch_bounds__(256) aggr_kernel(
    const float* __restrict__ in0, const float* __restrict__ W0, float* __restrict__ out0,
    const float* __restrict__ in1, const float* __restrict__ W1, float* __restrict__ out1,
    int tiles0)
{
    __shared__ float sW[64*64];
    __shared__ float sXT[64][68];

    const float *in, *W; float* out; int nrows, tile;
    if ((int)blockIdx.x < tiles0) { in = in0; W = W0; out = out0; nrows = N0; tile = blockIdx.x; }
    else                          { in = in1; W = W1; out = out1; nrows = N1; tile = blockIdx.x - tiles0; }

    int tid = threadIdx.x;
    for (int i = tid*4; i < 4096; i += 256*4)
        *(float4*)&sW[i] = *(const float4*)&W[i];

    int tx = tid & 15;
    int ty = tid >> 4;
    int row0 = tile << 6;

    #pragma unroll
    for (int i = 0; i < 4; i++) {
        int q  = tid + i*256;
        int r  = q >> 4;
        int c4 = (q & 15) << 2;
        float4 v = make_float4(0.f,0.f,0.f,0.f);
        if (row0 + r < nrows)
            v = *(const float4*)&in[(size_t)(row0 + r)*DIM + c4];
        sXT[c4+0][r] = v.x; sXT[c4+1][r] = v.y; sXT[c4+2][r] = v.z; sXT[c4+3][r] = v.w;
    }
    __syncthreads();

    float acc4[4][4] = {};
    #pragma unroll
    for (int k = 0; k < 64; k++) {
        float4 xv = *(float4*)&sXT[k][ty*4];
        float4 w  = *(float4*)&sW[k*64 + tx*4];
        float xr[4] = {xv.x, xv.y, xv.z, xv.w};
        float wc[4] = {w.x, w.y, w.z, w.w};
        #pragma unroll
        for (int r = 0; r < 4; r++)
            #pragma unroll
            for (int c = 0; c < 4; c++)
                acc4[r][c] += xr[r]*wc[c];
    }
    #pragma unroll
    for (int r = 0; r < 4; r++) {
        int row = row0 + ty*4 + r;
        if (row < nrows) {
            *(float4*)&out[(size_t)row*DIM + tx*4] =
                make_float4(fmaxf(acc4[r][0],0.f), fmaxf(acc4[r][1],0.f),
                            fmaxf(acc4[r][2],0.f), fmaxf(acc4[r][3],0.f));
        }
    }
}

// ---------------------------------------------------------------------------
extern "C" void kernel_launch(void* const* d_in, const int* in_sizes, int n_in,
                              void* d_out, int out_size) {
    const float* x0    = (const float*)d_in[0];
    const float* x1    = (const float*)d_in[1];
    const float* x2    = (const float*)d_in[2];
    const float* x3    = (const float*)d_in[3];
    const float* x4    = (const float*)d_in[4];
    const int*   adj0  = (const int*)  d_in[5];
    const float* adj0v = (const float*)d_in[6];
    const int*   adj1  = (const int*)  d_in[7];
    const float* adj1v = (const float*)d_in[8];
    const int*   inc   = (const int*)  d_in[9];
    const float* incv  = (const float*)d_in[10];
    const float* cci0  = (const float*)d_in[11];
    const float* cci1  = (const float*)d_in[12];
    const float* Whbs0 = (const float*)d_in[13];
    const float* a0    = (const float*)d_in[14];
    const float* Whbs1 = (const float*)d_in[15];
    const float* a1    = (const float*)d_in[16];
    const float* Ws    = (const float*)d_in[17];
    const float* Wt    = (const float*)d_in[18];
    const float* Wag0  = (const float*)d_in[19];
    const float* Wag1  = (const float*)d_in[20];
    float* out = (float*)d_out;

    float *pm, *psum; int* pcnt;
    cudaGetSymbolAddress((void**)&pm,   g_m);
    cudaGetSymbolAddress((void**)&psum, g_sum);
    cudaGetSymbolAddress((void**)&pcnt, g_cnt);

    float* pm0 = pm;
    float* pmt = pm + N0D;
    float* pm1 = pm + 2*(size_t)N0D;
    float* pms = pm + 2*(size_t)N0D + N1D;
    float* sum0 = psum;
    float* sum1 = psum + N0D;

    // zero histogram counters
    cudaMemsetAsync(pcnt, 0, NCNT*sizeof(int), 0);

    // Phase A: coef+count overlapped with x0 dual-GEMM
    phaseA_kernel<<<1480, 128>>>(x0, Whbs0, Wt, pm0, pmt,
                                 adj0, adj1, inc,
                                 adj0v, cci0, a0, adj1v, cci1, a1, 740);

    // offsets
    scan_pass1<<<NB, 256>>>();
    scan_pass2<<<1, 512>>>();
    scan_pass3<<<NB, 256>>>();

    // Phase C: fill overlapped with x1 dual-GEMM
    phaseC_kernel<<<2220, 128>>>(x1, Whbs1, Ws, pm1, pms,
                                 adj0, adj1, inc, incv, 1480);

    // combined atomic-free gather (warp per node)
    int totalWarps = N0 + N1;
    gather_kernel<<<(totalWarps*32 + 255)/256, 256>>>(pm0, pms, pm1, pmt, sum0, sum1);

    // merged epilogue GEMMs straight into d_out
    int tiles0 = (N0 + 63)/64, tiles1 = (N1 + 63)/64;
    aggr_kernel<<<tiles0 + tiles1, 256>>>(sum0, Wag0, out,
                                          sum1, Wag1, out + (size_t)N0*DIM, tiles0);

    // passthrough outputs
    size_t off2 = (size_t)(N0 + N1)*DIM;
    size_t off3 = off2 + (size_t)N2*DIM;
    size_t off4 = off3 + (size_t)N3*DIM;
    cudaMemcpyAsync(out + off2, x2, (size_t)N2*DIM*sizeof(float), cudaMemcpyDeviceToDevice, 0);
    cudaMemcpyAsync(out + off3, x3, (size_t)N3*DIM*sizeof(float), cudaMemcpyDeviceToDevice, 0);
    cudaMemcpyAsync(out + off4, x4, (size_t)N4*DIM*sizeof(float), cudaMemcpyDeviceToDevice, 0);
}

// round 9
// speedup vs baseline: 1.1796x; 1.1796x over previous
#include <cuda_runtime.h>
#include <cuda_fp16.h>
#include <cstdint>

#define N0 50000
#define N1 150000
#define N2 20000
#define N3 5000
#define N4 1000
#define E0 800000
#define E1 1500000
#define NNZ01 300000
#define DIM 64

#define N0D (N0*DIM)
#define N1D (N1*DIM)

#define ET   (E0 + E1 + 2*NNZ01)     // 2,900,000
#define NCNT (2*(N0 + N1))           // 400,000
#define B0 0
#define B1 (N0)
#define B2 (N0+N1)
#define B3 (N0+N1+N0)

#define SCAN_BLK 1024
#define NB ((NCNT + SCAN_BLK - 1)/SCAN_BLK)   // 391

// -------------------------- device scratch ---------------------------------
__device__ __half g_m[2*(N0D + N1D)];       // [m0 | mt | m1 | ms]  51MB fp16
__device__ float  g_sum[N0D + N1D];         // fp32 relu-sums       51MB
__device__ float  g_coef[E0 + E1];
__device__ int    g_cnt[NCNT];
__device__ int    g_offs[NCNT + 1];
__device__ int    g_bsums[NB + 1];
__device__ int2   g_rec[ET];                // {src, coef-as-int}   23MB

struct h4 { __half2 a, b; };

// ---------------------------------------------------------------------------
// Fused: histogram destinations + coef[e] = val[e] * dot(cci[e], a).
__global__ void count_kernel(const int* __restrict__ adj0, const int* __restrict__ adj1,
                             const int* __restrict__ inc,
                             const float* __restrict__ val0, const float* __restrict__ cci0,
                             const float* __restrict__ a0,
                             const float* __restrict__ val1, const float* __restrict__ cci1,
                             const float* __restrict__ a1) {
    int t = blockIdx.x * blockDim.x + threadIdx.x;
    if (t >= ET) return;
    int ci;
    if (t < E0) {
        ci = B0 + __ldg(&adj0[E0 + t]);
        const float* c = cci0 + (size_t)t*3;
        g_coef[t] = __ldg(&val0[t]) * (c[0]*a0[0] + c[1]*a0[1] + c[2]*a0[2]);
    } else if (t < E0 + E1) {
        int f = t - E0;
        ci = B1 + __ldg(&adj1[E1 + f]);
        const float* c = cci1 + (size_t)f*3;
        g_coef[E0 + f] = __ldg(&val1[f]) * (c[0]*a1[0] + c[1]*a1[1] + c[2]*a1[2]);
    } else if (t < E0 + E1 + NNZ01) {
        ci = B2 + __ldg(&inc[t - (E0 + E1)]);
    } else {
        ci = B3 + __ldg(&inc[NNZ01 + (t - (E0+E1+NNZ01))]);
    }
    atomicAdd(&g_cnt[ci], 1);
}

// --- 3-pass exclusive scan over g_cnt[NCNT] -> g_offs (non-destructive) ---
__global__ void scan_pass1() {
    __shared__ int wsum[8];
    int tid = threadIdx.x, lane = tid & 31, wid = tid >> 5;
    int base = blockIdx.x * SCAN_BLK + tid * 4;
    int4 v = make_int4(0,0,0,0);
    if (base < NCNT) v = *(const int4*)&g_cnt[base];
    int s = v.x + v.y + v.z + v.w;
    #pragma unroll
    for (int o = 16; o; o >>= 1) s += __shfl_down_sync(0xffffffffu, s, o);
    if (lane == 0) wsum[wid] = s;
    __syncthreads();
    if (tid == 0) {
        int tot = 0;
        #pragma unroll
        for (int i = 0; i < 8; i++) tot += wsum[i];
        g_bsums[blockIdx.x] = tot;
    }
}

__global__ void scan_pass2() {
    __shared__ int sm[512];
    int t = threadIdx.x;
    int v = (t < NB) ? g_bsums[t] : 0;
    sm[t] = v;
    __syncthreads();
    #pragma unroll
    for (int o = 1; o < 512; o <<= 1) {
        int add = (t >= o) ? sm[t - o] : 0;
        __syncthreads();
        sm[t] += add;
        __syncthreads();
    }
    if (t < NB) g_bsums[t] = sm[t] - v;
    if (t == 0) g_offs[NCNT] = ET;
}

__global__ void scan_pass3() {
    __shared__ int woff[8];
    int tid = threadIdx.x, lane = tid & 31, wid = tid >> 5;
    int base = blockIdx.x * SCAN_BLK + tid * 4;
    int4 v = make_int4(0,0,0,0);
    if (base < NCNT) v = *(const int4*)&g_cnt[base];
    int s = v.x + v.y + v.z + v.w;
    int incl = s;
    #pragma unroll
    for (int o = 1; o < 32; o <<= 1) {
        int n = __shfl_up_sync(0xffffffffu, incl, o);
        if (lane >= o) incl += n;
    }
    if (lane == 31) woff[wid] = incl;
    __syncthreads();
    if (tid == 0) {
        int acc = 0;
        #pragma unroll
        for (int i = 0; i < 8; i++) { int t2 = woff[i]; woff[i] = acc; acc += t2; }
    }
    __syncthreads();
    int excl = incl - s + woff[wid] + g_bsums[blockIdx.x];
    if (base < NCNT) {
        g_offs[base]     = excl;
        g_offs[base + 1] = excl + v.x;
        g_offs[base + 2] = excl + v.x + v.y;
        g_offs[base + 3] = excl + v.x + v.y + v.z;
    }
}

// fill: position = offs[ci] + (atomicSub(cnt[ci]) - 1); cnt consumed here.
__global__ void fill_kernel(const int* __restrict__ adj0, const int* __restrict__ adj1,
                            const int* __restrict__ inc, const float* __restrict__ incv) {
    int t = blockIdx.x * blockDim.x + threadIdx.x;
    if (t >= ET) return;
    int ci, src; float coef;
    if (t < E0) {
        ci   = B0 + __ldg(&adj0[E0 + t]);
        src  = __ldg(&adj0[t]);
        coef = g_coef[t];
    } else if (t < E0 + E1) {
        int f = t - E0;
        ci   = B1 + __ldg(&adj1[E1 + f]);
        src  = __ldg(&adj1[f]);
        coef = g_coef[E0 + f];
    } else if (t < E0 + E1 + NNZ01) {
        int f = t - (E0 + E1);
        ci   = B2 + __ldg(&inc[f]);
        src  = __ldg(&inc[NNZ01 + f]);
        coef = __ldg(&incv[f]);
    } else {
        int f = t - (E0 + E1 + NNZ01);
        ci   = B3 + __ldg(&inc[NNZ01 + f]);
        src  = __ldg(&inc[f]);
        coef = __ldg(&incv[f]);
    }
    int pos = g_offs[ci] + (atomicSub(&g_cnt[ci], 1) - 1);
    g_rec[pos] = make_int2(src, __float_as_int(coef));
}

// ---------------------------------------------------------------------------
// Dual GEMM: outA = x @ WA, outB = x @ WB, outputs fp16.
__global__ void __launch_bounds__(128) gemm_dual_kernel(
    const float* __restrict__ x, const float* __restrict__ WA, const float* __restrict__ WB,
    __half* __restrict__ outA, __half* __restrict__ outB, int nrows)
{
    __shared__ float sWA[64*64];
    __shared__ float sWB[64*64];
    __shared__ float sXT[64][36];

    int tid = threadIdx.x;
    for (int i = tid*4; i < 4096; i += 128*4) {
        *(float4*)&sWA[i] = *(const float4*)&WA[i];
        *(float4*)&sWB[i] = *(const float4*)&WB[i];
    }
    int ntiles = (nrows + 31) >> 5;
    int tx = tid & 15;
    int ty = tid >> 4;

    for (int tile = blockIdx.x; tile < ntiles; tile += gridDim.x) {
        int row0 = tile << 5;
        __syncthreads();
        #pragma unroll
        for (int i = 0; i < 4; i++) {
            int q  = tid + i*128;
            int r  = q >> 4;
            int c4 = (q & 15) << 2;
            float4 v = make_float4(0.f,0.f,0.f,0.f);
            if (row0 + r < nrows) v = *(const float4*)&x[(size_t)(row0 + r)*DIM + c4];
            sXT[c4+0][r] = v.x; sXT[c4+1][r] = v.y; sXT[c4+2][r] = v.z; sXT[c4+3][r] = v.w;
        }
        __syncthreads();

        float aA[4][4] = {}; float aB[4][4] = {};
        #pragma unroll
        for (int k = 0; k < 64; k++) {
            float4 xv = *(float4*)&sXT[k][ty*4];
            float4 wa = *(float4*)&sWA[k*64 + tx*4];
            float4 wb = *(float4*)&sWB[k*64 + tx*4];
            float xr[4]  = {xv.x, xv.y, xv.z, xv.w};
            float wac[4] = {wa.x, wa.y, wa.z, wa.w};
            float wbc[4] = {wb.x, wb.y, wb.z, wb.w};
            #pragma unroll
            for (int r = 0; r < 4; r++)
                #pragma unroll
                for (int c = 0; c < 4; c++) {
                    aA[r][c] += xr[r]*wac[c];
                    aB[r][c] += xr[r]*wbc[c];
                }
        }
        #pragma unroll
        for (int r = 0; r < 4; r++) {
            int row = row0 + ty*4 + r;
            if (row < nrows) {
                h4 pa, pb;
                pa.a = __floats2half2_rn(aA[r][0], aA[r][1]);
                pa.b = __floats2half2_rn(aA[r][2], aA[r][3]);
                pb.a = __floats2half2_rn(aB[r][0], aB[r][1]);
                pb.b = __floats2half2_rn(aB[r][2], aB[r][3]);
                *(h4*)&outA[(size_t)row*DIM + tx*4] = pa;
                *(h4*)&outB[(size_t)row*DIM + tx*4] = pb;
            }
        }
    }
}

// ---------------------------------------------------------------------------
// Warp-per-node CSR gather. Lane owns 2 cols; fp16 message rows, fp32 accum.
__device__ __forceinline__ float2 seg_accum(const __half* __restrict__ m,
                                            int s, int e, int lane) {
    float2 acc = make_float2(0.f, 0.f);
    for (int base = s; base < e; base += 32) {
        int idx = base + lane;
        int2 rv = (idx < e) ? __ldg(&g_rec[idx]) : make_int2(0, 0);
        int cnt = min(32, e - base);
        int j = 0;
        for (; j + 4 <= cnt; j += 4) {
            int  s0 = __shfl_sync(0xffffffffu, rv.x, j+0);
            int  s1 = __shfl_sync(0xffffffffu, rv.x, j+1);
            int  s2 = __shfl_sync(0xffffffffu, rv.x, j+2);
            int  s3 = __shfl_sync(0xffffffffu, rv.x, j+3);
            float c0 = __int_as_float(__shfl_sync(0xffffffffu, rv.y, j+0));
            float c1 = __int_as_float(__shfl_sync(0xffffffffu, rv.y, j+1));
            float c2 = __int_as_float(__shfl_sync(0xffffffffu, rv.y, j+2));
            float c3 = __int_as_float(__shfl_sync(0xffffffffu, rv.y, j+3));
            float2 v0 = __half22float2(*(const __half2*)&m[(size_t)s0*DIM + lane*2]);
            float2 v1 = __half22float2(*(const __half2*)&m[(size_t)s1*DIM + lane*2]);
            float2 v2 = __half22float2(*(const __half2*)&m[(size_t)s2*DIM + lane*2]);
            float2 v3 = __half22float2(*(const __half2*)&m[(size_t)s3*DIM + lane*2]);
            acc.x += c0*v0.x; acc.y += c0*v0.y;
            acc.x += c1*v1.x; acc.y += c1*v1.y;
            acc.x += c2*v2.x; acc.y += c2*v2.y;
            acc.x += c3*v3.x; acc.y += c3*v3.y;
        }
        for (; j < cnt; j++) {
            int   sj = __shfl_sync(0xffffffffu, rv.x, j);
            float cj = __int_as_float(__shfl_sync(0xffffffffu, rv.y, j));
            float2 v = __half22float2(*(const __half2*)&m[(size_t)sj*DIM + lane*2]);
            acc.x += cj*v.x; acc.y += cj*v.y;
        }
    }
    return acc;
}

__global__ void __launch_bounds__(256) gather_kernel(
    const __half* __restrict__ pm0, const __half* __restrict__ pms,
    const __half* __restrict__ pm1, const __half* __restrict__ pmt,
    float* __restrict__ sum0, float* __restrict__ sum1)
{
    int w    = (blockIdx.x * blockDim.x + threadIdx.x) >> 5;
    int lane = threadIdx.x & 31;
    if (w >= N0 + N1) return;

    const __half *mA, *mB; float* outp; int node, baseA, baseB;
    if (w < N0) { node = w;      mA = pm0; baseA = B0; mB = pms; baseB = B2; outp = sum0; }
    else        { node = w - N0; mA = pm1; baseA = B1; mB = pmt; baseB = B3; outp = sum1; }

    int sA = g_offs[baseA + node], eA = g_offs[baseA + node + 1];
    int sB = g_offs[baseB + node], eB = g_offs[baseB + node + 1];
    float2 a = seg_accum(mA, sA, eA, lane);
    float2 b = seg_accum(mB, sB, eB, lane);
    float2 r;
    r.x = fmaxf(a.x, 0.f) + fmaxf(b.x, 0.f);
    r.y = fmaxf(a.y, 0.f) + fmaxf(b.y, 0.f);
    *(float2*)&outp[(size_t)node*DIM + lane*2] = r;
}

// ---------------------------------------------------------------------------
// Merged epilogue: out = relu(in @ W) for both node families in one launch.
__global__ void __launch_bounds__(256) aggr_kernel(
    const float* __restrict__ in0, const float* __restrict__ W0, float* __restrict__ out0,
    const float* __restrict__ in1, const float* __restrict__ W1, float* __restrict__ out1,
    int tiles0)
{
    __shared__ float sW[64*64];
    __shared__ float sXT[64][68];

    const float *in, *W; float* out; int nrows, tile;
    if ((int)blockIdx.x < tiles0) { in = in0; W = W0; out = out0; nrows = N0; tile = blockIdx.x; }
    else                          { in = in1; W = W1; out = out1; nrows = N1; tile = blockIdx.x - tiles0; }

    int tid = threadIdx.x;
    for (int i = tid*4; i < 4096; i += 256*4)
        *(float4*)&sW[i] = *(const float4*)&W[i];

    int tx = tid & 15;
    int ty = tid >> 4;
    int row0 = tile << 6;

    #pragma unroll
    for (int i = 0; i < 4; i++) {
        int q  = tid + i*256;
        int r  = q >> 4;
        int c4 = (q & 15) << 2;
        float4 v = make_float4(0.f,0.f,0.f,0.f);
        if (row0 + r < nrows)
            v = *(const float4*)&in[(size_t)(row0 + r)*DIM + c4];
        sXT[c4+0][r] = v.x; sXT[c4+1][r] = v.y; sXT[c4+2][r] = v.z; sXT[c4+3][r] = v.w;
    }
    __syncthreads();

    float acc4[4][4] = {};
    #pragma unroll
    for (int k = 0; k < 64; k++) {
        float4 xv = *(float4*)&sXT[k][ty*4];
        float4 w  = *(float4*)&sW[k*64 + tx*4];
        float xr[4] = {xv.x, xv.y, xv.z, xv.w};
        float wc[4] = {w.x, w.y, w.z, w.w};
        #pragma unroll
        for (int r = 0; r < 4; r++)
            #pragma unroll
            for (int c = 0; c < 4; c++)
                acc4[r][c] += xr[r]*wc[c];
    }
    #pragma unroll
    for (int r = 0; r < 4; r++) {
        int row = row0 + ty*4 + r;
        if (row < nrows) {
            *(float4*)&out[(size_t)row*DIM + tx*4] =
                make_float4(fmaxf(acc4[r][0],0.f), fmaxf(acc4[r][1],0.f),
                            fmaxf(acc4[r][2],0.f), fmaxf(acc4[r][3],0.f));
        }
    }
}

// ---------------------------------------------------------------------------
extern "C" void kernel_launch(void* const* d_in, const int* in_sizes, int n_in,
                              void* d_out, int out_size) {
    const float* x0    = (const float*)d_in[0];
    const float* x1    = (const float*)d_in[1];
    const float* x2    = (const float*)d_in[2];
    const float* x3    = (const float*)d_in[3];
    const float* x4    = (const float*)d_in[4];
    const int*   adj0  = (const int*)  d_in[5];
    const float* adj0v = (const float*)d_in[6];
    const int*   adj1  = (const int*)  d_in[7];
    const float* adj1v = (const float*)d_in[8];
    const int*   inc   = (const int*)  d_in[9];
    const float* incv  = (const float*)d_in[10];
    const float* cci0  = (const float*)d_in[11];
    const float* cci1  = (const float*)d_in[12];
    const float* Whbs0 = (const float*)d_in[13];
    const float* a0    = (const float*)d_in[14];
    const float* Whbs1 = (const float*)d_in[15];
    const float* a1    = (const float*)d_in[16];
    const float* Ws    = (const float*)d_in[17];
    const float* Wt    = (const float*)d_in[18];
    const float* Wag0  = (const float*)d_in[19];
    const float* Wag1  = (const float*)d_in[20];
    float* out = (float*)d_out;

    __half *pm; float *psum; int* pcnt;
    cudaGetSymbolAddress((void**)&pm,   g_m);
    cudaGetSymbolAddress((void**)&psum, g_sum);
    cudaGetSymbolAddress((void**)&pcnt, g_cnt);

    __half* pm0 = pm;
    __half* pmt = pm + N0D;
    __half* pm1 = pm + 2*(size_t)N0D;
    __half* pms = pm + 2*(size_t)N0D + N1D;
    float* sum0 = psum;
    float* sum1 = psum + N0D;

    // binning chain (coef fused into count)
    cudaMemsetAsync(pcnt, 0, NCNT*sizeof(int), 0);
    count_kernel<<<(ET + 255)/256, 256>>>(adj0, adj1, inc,
                                          adj0v, cci0, a0, adj1v, cci1, a1);
    scan_pass1<<<NB, 256>>>();
    scan_pass2<<<1, 512>>>();
    scan_pass3<<<NB, 256>>>();
    fill_kernel<<<(ET + 255)/256, 256>>>(adj0, adj1, inc, incv);

    // dense projections (fp16 outputs; keep hot in L2 for the gather)
    gemm_dual_kernel<<<740, 128>>>(x0, Whbs0, Wt, pm0, pmt, N0);
    gemm_dual_kernel<<<740, 128>>>(x1, Whbs1, Ws, pm1, pms, N1);

    // merged atomic-free gather (warp per node)
    gather_kernel<<<((N0 + N1)*32 + 255)/256, 256>>>(pm0, pms, pm1, pmt, sum0, sum1);

    // merged epilogue GEMMs straight into d_out
    int tiles0 = (N0 + 63)/64, tiles1 = (N1 + 63)/64;
    aggr_kernel<<<tiles0 + tiles1, 256>>>(sum0, Wag0, out,
                                          sum1, Wag1, out + (size_t)N0*DIM, tiles0);

    // passthrough outputs
    size_t off2 = (size_t)(N0 + N1)*DIM;
    size_t off3 = off2 + (size_t)N2*DIM;
    size_t off4 = off3 + (size_t)N3*DIM;
    cudaMemcpyAsync(out + off2, x2, (size_t)N2*DIM*sizeof(float), cudaMemcpyDeviceToDevice, 0);
    cudaMemcpyAsync(out + off3, x3, (size_t)N3*DIM*sizeof(float), cudaMemcpyDeviceToDevice, 0);
    cudaMemcpyAsync(out + off4, x4, (size_t)N4*DIM*sizeof(float), cudaMemcpyDeviceToDevice, 0);
}

// round 11
// speedup vs baseline: 1.1863x; 1.0057x over previous
#include <cuda_runtime.h>
#include <cuda_fp16.h>
#include <cstdint>

#define N0 50000
#define N1 150000
#define N2 20000
#define N3 5000
#define N4 1000
#define E0 800000
#define E1 1500000
#define NNZ01 300000
#define DIM 64

#define N0D (N0*DIM)
#define N1D (N1*DIM)

#define ET   (E0 + E1 + 2*NNZ01)     // 2,900,000
#define NCNT (2*(N0 + N1))           // 400,000
#define B0 0
#define B1 (N0)
#define B2 (N0+N1)
#define B3 (N0+N1+N0)

#define SCAN_BLK 1024
#define NB ((NCNT + SCAN_BLK - 1)/SCAN_BLK)   // 391

// -------------------------- device scratch ---------------------------------
__device__ __half g_m[2*(N0D + N1D)];       // [m0 | mt | m1 | ms]  51MB fp16
__device__ float  g_sum[N0D + N1D];         // fp32 relu-sums       51MB
__device__ float  g_coef[E0 + E1];
__device__ int    g_cnt[NCNT];
__device__ int    g_offs[NCNT + 1];
__device__ int    g_bsums[NB + 1];
__device__ int2   g_rec[ET];                // {src, coef-as-int}   23MB

struct h4 { __half2 a, b; };

// -------------------- streams/events (created pre-capture) ------------------
// Static initializer runs at load time, before the harness's first
// kernel_launch call and before graph capture. No device memory is allocated.
struct StreamCtx {
    cudaStream_t s1, s2;
    cudaEvent_t  evRoot, evFill, evCpy;
    StreamCtx() {
        cudaStreamCreateWithFlags(&s1, cudaStreamNonBlocking);
        cudaStreamCreateWithFlags(&s2, cudaStreamNonBlocking);
        cudaEventCreateWithFlags(&evRoot, cudaEventDisableTiming);
        cudaEventCreateWithFlags(&evFill, cudaEventDisableTiming);
        cudaEventCreateWithFlags(&evCpy,  cudaEventDisableTiming);
    }
};
static StreamCtx g_sc;

// ---------------------------------------------------------------------------
// Fused: histogram destinations + coef[e] = val[e] * dot(cci[e], a).
__global__ void count_kernel(const int* __restrict__ adj0, const int* __restrict__ adj1,
                             const int* __restrict__ inc,
                             const float* __restrict__ val0, const float* __restrict__ cci0,
                             const float* __restrict__ a0,
                             const float* __restrict__ val1, const float* __restrict__ cci1,
                             const float* __restrict__ a1) {
    int t = blockIdx.x * blockDim.x + threadIdx.x;
    if (t >= ET) return;
    int ci;
    if (t < E0) {
        ci = B0 + __ldg(&adj0[E0 + t]);
        const float* c = cci0 + (size_t)t*3;
        g_coef[t] = __ldg(&val0[t]) * (c[0]*a0[0] + c[1]*a0[1] + c[2]*a0[2]);
    } else if (t < E0 + E1) {
        int f = t - E0;
        ci = B1 + __ldg(&adj1[E1 + f]);
        const float* c = cci1 + (size_t)f*3;
        g_coef[E0 + f] = __ldg(&val1[f]) * (c[0]*a1[0] + c[1]*a1[1] + c[2]*a1[2]);
    } else if (t < E0 + E1 + NNZ01) {
        ci = B2 + __ldg(&inc[t - (E0 + E1)]);
    } else {
        ci = B3 + __ldg(&inc[NNZ01 + (t - (E0+E1+NNZ01))]);
    }
    atomicAdd(&g_cnt[ci], 1);
}

// --- 3-pass exclusive scan over g_cnt[NCNT] -> g_offs (non-destructive) ---
__global__ void scan_pass1() {
    __shared__ int wsum[8];
    int tid = threadIdx.x, lane = tid & 31, wid = tid >> 5;
    int base = blockIdx.x * SCAN_BLK + tid * 4;
    int4 v = make_int4(0,0,0,0);
    if (base < NCNT) v = *(const int4*)&g_cnt[base];
    int s = v.x + v.y + v.z + v.w;
    #pragma unroll
    for (int o = 16; o; o >>= 1) s += __shfl_down_sync(0xffffffffu, s, o);
    if (lane == 0) wsum[wid] = s;
    __syncthreads();
    if (tid == 0) {
        int tot = 0;
        #pragma unroll
        for (int i = 0; i < 8; i++) tot += wsum[i];
        g_bsums[blockIdx.x] = tot;
    }
}

__global__ void scan_pass2() {
    __shared__ int sm[512];
    int t = threadIdx.x;
    int v = (t < NB) ? g_bsums[t] : 0;
    sm[t] = v;
    __syncthreads();
    #pragma unroll
    for (int o = 1; o < 512; o <<= 1) {
        int add = (t >= o) ? sm[t - o] : 0;
        __syncthreads();
        sm[t] += add;
        __syncthreads();
    }
    if (t < NB) g_bsums[t] = sm[t] - v;
    if (t == 0) g_offs[NCNT] = ET;
}

__global__ void scan_pass3() {
    __shared__ int woff[8];
    int tid = threadIdx.x, lane = tid & 31, wid = tid >> 5;
    int base = blockIdx.x * SCAN_BLK + tid * 4;
    int4 v = make_int4(0,0,0,0);
    if (base < NCNT) v = *(const int4*)&g_cnt[base];
    int s = v.x + v.y + v.z + v.w;
    int incl = s;
    #pragma unroll
    for (int o = 1; o < 32; o <<= 1) {
        int n = __shfl_up_sync(0xffffffffu, incl, o);
        if (lane >= o) incl += n;
    }
    if (lane == 31) woff[wid] = incl;
    __syncthreads();
    if (tid == 0) {
        int acc = 0;
        #pragma unroll
        for (int i = 0; i < 8; i++) { int t2 = woff[i]; woff[i] = acc; acc += t2; }
    }
    __syncthreads();
    int excl = incl - s + woff[wid] + g_bsums[blockIdx.x];
    if (base < NCNT) {
        g_offs[base]     = excl;
        g_offs[base + 1] = excl + v.x;
        g_offs[base + 2] = excl + v.x + v.y;
        g_offs[base + 3] = excl + v.x + v.y + v.z;
    }
}

// fill: position = offs[ci] + (atomicSub(cnt[ci]) - 1); cnt consumed here.
__global__ void fill_kernel(const int* __restrict__ adj0, const int* __restrict__ adj1,
                            const int* __restrict__ inc, const float* __restrict__ incv) {
    int t = blockIdx.x * blockDim.x + threadIdx.x;
    if (t >= ET) return;
    int ci, src; float coef;
    if (t < E0) {
        ci   = B0 + __ldg(&adj0[E0 + t]);
        src  = __ldg(&adj0[t]);
        coef = g_coef[t];
    } else if (t < E0 + E1) {
        int f = t - E0;
        ci   = B1 + __ldg(&adj1[E1 + f]);
        src  = __ldg(&adj1[f]);
        coef = g_coef[E0 + f];
    } else if (t < E0 + E1 + NNZ01) {
        int f = t - (E0 + E1);
        ci   = B2 + __ldg(&inc[f]);
        src  = __ldg(&inc[NNZ01 + f]);
        coef = __ldg(&incv[f]);
    } else {
        int f = t - (E0 + E1 + NNZ01);
        ci   = B3 + __ldg(&inc[NNZ01 + f]);
        src  = __ldg(&inc[f]);
        coef = __ldg(&incv[f]);
    }
    int pos = g_offs[ci] + (atomicSub(&g_cnt[ci], 1) - 1);
    g_rec[pos] = make_int2(src, __float_as_int(coef));
}

// ---------------------------------------------------------------------------
// Dual GEMM: outA = x @ WA, outB = x @ WB, outputs fp16.
__global__ void __launch_bounds__(128) gemm_dual_kernel(
    const float* __restrict__ x, const float* __restrict__ WA, const float* __restrict__ WB,
    __half* __restrict__ outA, __half* __restrict__ outB, int nrows)
{
    __shared__ float sWA[64*64];
    __shared__ float sWB[64*64];
    __shared__ float sXT[64][36];

    int tid = threadIdx.x;
    for (int i = tid*4; i < 4096; i += 128*4) {
        *(float4*)&sWA[i] = *(const float4*)&WA[i];
        *(float4*)&sWB[i] = *(const float4*)&WB[i];
    }
    int ntiles = (nrows + 31) >> 5;
    int tx = tid & 15;
    int ty = tid >> 4;

    for (int tile = blockIdx.x; tile < ntiles; tile += gridDim.x) {
        int row0 = tile << 5;
        __syncthreads();
        #pragma unroll
        for (int i = 0; i < 4; i++) {
            int q  = tid + i*128;
            int r  = q >> 4;
            int c4 = (q & 15) << 2;
            float4 v = make_float4(0.f,0.f,0.f,0.f);
            if (row0 + r < nrows) v = *(const float4*)&x[(size_t)(row0 + r)*DIM + c4];
            sXT[c4+0][r] = v.x; sXT[c4+1][r] = v.y; sXT[c4+2][r] = v.z; sXT[c4+3][r] = v.w;
        }
        __syncthreads();

        float aA[4][4] = {}; float aB[4][4] = {};
        #pragma unroll
        for (int k = 0; k < 64; k++) {
            float4 xv = *(float4*)&sXT[k][ty*4];
            float4 wa = *(float4*)&sWA[k*64 + tx*4];
            float4 wb = *(float4*)&sWB[k*64 + tx*4];
            float xr[4]  = {xv.x, xv.y, xv.z, xv.w};
            float wac[4] = {wa.x, wa.y, wa.z, wa.w};
            float wbc[4] = {wb.x, wb.y, wb.z, wb.w};
            #pragma unroll
            for (int r = 0; r < 4; r++)
                #pragma unroll
                for (int c = 0; c < 4; c++) {
                    aA[r][c] += xr[r]*wac[c];
                    aB[r][c] += xr[r]*wbc[c];
                }
        }
        #pragma unroll
        for (int r = 0; r < 4; r++) {
            int row = row0 + ty*4 + r;
            if (row < nrows) {
                h4 pa, pb;
                pa.a = __floats2half2_rn(aA[r][0], aA[r][1]);
                pa.b = __floats2half2_rn(aA[r][2], aA[r][3]);
                pb.a = __floats2half2_rn(aB[r][0], aB[r][1]);
                pb.b = __floats2half2_rn(aB[r][2], aB[r][3]);
                *(h4*)&outA[(size_t)row*DIM + tx*4] = pa;
                *(h4*)&outB[(size_t)row*DIM + tx*4] = pb;
            }
        }
    }
}

// ---------------------------------------------------------------------------
// Warp-per-node CSR gather. Lane owns 2 cols; fp16 message rows, fp32 accum.
__device__ __forceinline__ float2 seg_accum(const __half* __restrict__ m,
                                            int s, int e, int lane) {
    float2 acc = make_float2(0.f, 0.f);
    for (int base = s; base < e; base += 32) {
        int idx = base + lane;
        int2 rv = (idx < e) ? __ldg(&g_rec[idx]) : make_int2(0, 0);
        int cnt = min(32, e - base);
        int j = 0;
        for (; j + 4 <= cnt; j += 4) {
            int  s0 = __shfl_sync(0xffffffffu, rv.x, j+0);
            int  s1 = __shfl_sync(0xffffffffu, rv.x, j+1);
            int  s2 = __shfl_sync(0xffffffffu, rv.x, j+2);
            int  s3 = __shfl_sync(0xffffffffu, rv.x, j+3);
            float c0 = __int_as_float(__shfl_sync(0xffffffffu, rv.y, j+0));
            float c1 = __int_as_float(__shfl_sync(0xffffffffu, rv.y, j+1));
            float c2 = __int_as_float(__shfl_sync(0xffffffffu, rv.y, j+2));
            float c3 = __int_as_float(__shfl_sync(0xffffffffu, rv.y, j+3));
            float2 v0 = __half22float2(*(const __half2*)&m[(size_t)s0*DIM + lane*2]);
            float2 v1 = __half22float2(*(const __half2*)&m[(size_t)s1*DIM + lane*2]);
            float2 v2 = __half22float2(*(const __half2*)&m[(size_t)s2*DIM + lane*2]);
            float2 v3 = __half22float2(*(const __half2*)&m[(size_t)s3*DIM + lane*2]);
            acc.x += c0*v0.x; acc.y += c0*v0.y;
            acc.x += c1*v1.x; acc.y += c1*v1.y;
            acc.x += c2*v2.x; acc.y += c2*v2.y;
            acc.x += c3*v3.x; acc.y += c3*v3.y;
        }
        for (; j < cnt; j++) {
            int   sj = __shfl_sync(0xffffffffu, rv.x, j);
            float cj = __int_as_float(__shfl_sync(0xffffffffu, rv.y, j));
            float2 v = __half22float2(*(const __half2*)&m[(size_t)sj*DIM + lane*2]);
            acc.x += cj*v.x; acc.y += cj*v.y;
        }
    }
    return acc;
}

__global__ void __launch_bounds__(256) gather_kernel(
    const __half* __restrict__ pm0, const __half* __restrict__ pms,
    const __half* __restrict__ pm1, const __half* __restrict__ pmt,
    float* __restrict__ sum0, float* __restrict__ sum1)
{
    int w    = (blockIdx.x * blockDim.x + threadIdx.x) >> 5;
    int lane = threadIdx.x & 31;
    if (w >= N0 + N1) return;

    const __half *mA, *mB; float* outp; int node, baseA, baseB;
    if (w < N0) { node = w;      mA = pm0; baseA = B0; mB = pms; baseB = B2; outp = sum0; }
    else        { node = w - N0; mA = pm1; baseA = B1; mB = pmt; baseB = B3; outp = sum1; }

    int sA = g_offs[baseA + node], eA = g_offs[baseA + node + 1];
    int sB = g_offs[baseB + node], eB = g_offs[baseB + node + 1];
    float2 a = seg_accum(mA, sA, eA, lane);
    float2 b = seg_accum(mB, sB, eB, lane);
    float2 r;
    r.x = fmaxf(a.x, 0.f) + fmaxf(b.x, 0.f);
    r.y = fmaxf(a.y, 0.f) + fmaxf(b.y, 0.f);
    *(float2*)&outp[(size_t)node*DIM + lane*2] = r;
}

// ---------------------------------------------------------------------------
// Merged epilogue: out = relu(in @ W) for both node families in one launch.
__global__ void __launch_bounds__(256) aggr_kernel(
    const float* __restrict__ in0, const float* __restrict__ W0, float* __restrict__ out0,
    const float* __restrict__ in1, const float* __restrict__ W1, float* __restrict__ out1,
    int tiles0)
{
    __shared__ float sW[64*64];
    __shared__ float sXT[64][68];

    const float *in, *W; float* out; int nrows, tile;
    if ((int)blockIdx.x < tiles0) { in = in0; W = W0; out = out0; nrows = N0; tile = blockIdx.x; }
    else                          { in = in1; W = W1; out = out1; nrows = N1; tile = blockIdx.x - tiles0; }

    int tid = threadIdx.x;
    for (int i = tid*4; i < 4096; i += 256*4)
        *(float4*)&sW[i] = *(const float4*)&W[i];

    int tx = tid & 15;
    int ty = tid >> 4;
    int row0 = tile << 6;

    #pragma unroll
    for (int i = 0; i < 4; i++) {
        int q  = tid + i*256;
        int r  = q >> 4;
        int c4 = (q & 15) << 2;
        float4 v = make_float4(0.f,0.f,0.f,0.f);
        if (row0 + r < nrows)
            v = *(const float4*)&in[(size_t)(row0 + r)*DIM + c4];
        sXT[c4+0][r] = v.x; sXT[c4+1][r] = v.y; sXT[c4+2][r] = v.z; sXT[c4+3][r] = v.w;
    }
    __syncthreads();

    float acc4[4][4] = {};
    #pragma unroll
    for (int k = 0; k < 64; k++) {
        float4 xv = *(float4*)&sXT[k][ty*4];
        float4 w  = *(float4*)&sW[k*64 + tx*4];
        float xr[4] = {xv.x, xv.y, xv.z, xv.w};
        float wc[4] = {w.x, w.y, w.z, w.w};
        #pragma unroll
        for (int r = 0; r < 4; r++)
            #pragma unroll
            for (int c = 0; c < 4; c++)
                acc4[r][c] += xr[r]*wc[c];
    }
    #pragma unroll
    for (int r = 0; r < 4; r++) {
        int row = row0 + ty*4 + r;
        if (row < nrows) {
            *(float4*)&out[(size_t)row*DIM + tx*4] =
                make_float4(fmaxf(acc4[r][0],0.f), fmaxf(acc4[r][1],0.f),
                            fmaxf(acc4[r][2],0.f), fmaxf(acc4[r][3],0.f));
        }
    }
}

// ---------------------------------------------------------------------------
extern "C" void kernel_launch(void* const* d_in, const int* in_sizes, int n_in,
                              void* d_out, int out_size) {
    const float* x0    = (const float*)d_in[0];
    const float* x1    = (const float*)d_in[1];
    const float* x2    = (const float*)d_in[2];
    const float* x3    = (const float*)d_in[3];
    const float* x4    = (const float*)d_in[4];
    const int*   adj0  = (const int*)  d_in[5];
    const float* adj0v = (const float*)d_in[6];
    const int*   adj1  = (const int*)  d_in[7];
    const float* adj1v = (const float*)d_in[8];
    const int*   inc   = (const int*)  d_in[9];
    const float* incv  = (const float*)d_in[10];
    const float* cci0  = (const float*)d_in[11];
    const float* cci1  = (const float*)d_in[12];
    const float* Whbs0 = (const float*)d_in[13];
    const float* a0    = (const float*)d_in[14];
    const float* Whbs1 = (const float*)d_in[15];
    const float* a1    = (const float*)d_in[16];
    const float* Ws    = (const float*)d_in[17];
    const float* Wt    = (const float*)d_in[18];
    const float* Wag0  = (const float*)d_in[19];
    const float* Wag1  = (const float*)d_in[20];
    float* out = (float*)d_out;

    __half *pm; float *psum; int* pcnt;
    cudaGetSymbolAddress((void**)&pm,   g_m);
    cudaGetSymbolAddress((void**)&psum, g_sum);
    cudaGetSymbolAddress((void**)&pcnt, g_cnt);

    __half* pm0 = pm;
    __half* pmt = pm + N0D;
    __half* pm1 = pm + 2*(size_t)N0D;
    __half* pms = pm + 2*(size_t)N0D + N1D;
    float* sum0 = psum;
    float* sum1 = psum + N0D;

    cudaStream_t s1 = g_sc.s1, s2 = g_sc.s2;

    // fork: root event on the capturing stream
    cudaEventRecord(g_sc.evRoot, 0);
    cudaStreamWaitEvent(s1, g_sc.evRoot, 0);
    cudaStreamWaitEvent(s2, g_sc.evRoot, 0);

    // branch s1: binning chain (independent of GEMMs)
    cudaMemsetAsync(pcnt, 0, NCNT*sizeof(int), s1);
    count_kernel<<<(ET + 255)/256, 256, 0, s1>>>(adj0, adj1, inc,
                                                 adj0v, cci0, a0, adj1v, cci1, a1);
    scan_pass1<<<NB, 256, 0, s1>>>();
    scan_pass2<<<1, 512, 0, s1>>>();
    scan_pass3<<<NB, 256, 0, s1>>>();
    fill_kernel<<<(ET + 255)/256, 256, 0, s1>>>(adj0, adj1, inc, incv);
    cudaEventRecord(g_sc.evFill, s1);

    // branch s2: passthrough copies (DMA engines)
    size_t off2 = (size_t)(N0 + N1)*DIM;
    size_t off3 = off2 + (size_t)N2*DIM;
    size_t off4 = off3 + (size_t)N3*DIM;
    cudaMemcpyAsync(out + off2, x2, (size_t)N2*DIM*sizeof(float), cudaMemcpyDeviceToDevice, s2);
    cudaMemcpyAsync(out + off3, x3, (size_t)N3*DIM*sizeof(float), cudaMemcpyDeviceToDevice, s2);
    cudaMemcpyAsync(out + off4, x4, (size_t)N4*DIM*sizeof(float), cudaMemcpyDeviceToDevice, s2);
    cudaEventRecord(g_sc.evCpy, s2);

    // branch 0: dense projections (run concurrently with s1/s2)
    gemm_dual_kernel<<<740, 128>>>(x0, Whbs0, Wt, pm0, pmt, N0);
    gemm_dual_kernel<<<740, 128>>>(x1, Whbs1, Ws, pm1, pms, N1);

    // join: gather needs fill + both GEMMs
    cudaStreamWaitEvent(0, g_sc.evFill, 0);
    gather_kernel<<<((N0 + N1)*32 + 255)/256, 256>>>(pm0, pms, pm1, pmt, sum0, sum1);

    // epilogue GEMMs straight into d_out
    int tiles0 = (N0 + 63)/64, tiles1 = (N1 + 63)/64;
    aggr_kernel<<<tiles0 + tiles1, 256>>>(sum0, Wag0, out,
                                          sum1, Wag1, out + (size_t)N0*DIM, tiles0);

    // join copies back into the capturing stream before return
    cudaStreamWaitEvent(0, g_sc.evCpy, 0);
}

// round 14
// speedup vs baseline: 1.2761x; 1.0757x over previous
#include <cuda_runtime.h>
#include <cuda_fp16.h>
#include <cstdint>

#define N0 50000
#define N1 150000
#define N2 20000
#define N3 5000
#define N4 1000
#define E0 800000
#define E1 1500000
#define NNZ01 300000
#define DIM 64

#define N0D (N0*DIM)
#define N1D (N1*DIM)

#define ET   (E0 + E1 + 2*NNZ01)     // 2,900,000
#define NCNT (2*(N0 + N1))           // 400,000
#define B0 0
#define B1 (N0)
#define B2 (N0+N1)
#define B3 (N0+N1+N0)

#define SCAN_BLK 1024
#define NB ((NCNT + SCAN_BLK - 1)/SCAN_BLK)   // 391

// -------------------------- device scratch ---------------------------------
__device__ __half g_m[2*(N0D + N1D)];       // [m0 | mt | m1 | ms]  51MB fp16
__device__ float  g_sum[N0D + N1D];         // fp32 relu-sums       51MB
__device__ float  g_coef[E0 + E1];
__device__ int    g_cnt[NCNT];
__device__ int    g_offs[NCNT + 1];
__device__ int    g_bsums[NB + 1];
__device__ int2   g_rec[ET];                // {src, coef-as-int}   23MB

struct h4 { __half2 a, b; };

// -------------------- streams/events (created pre-capture) ------------------
struct StreamCtx {
    cudaStream_t s1, s2;
    cudaEvent_t  evRoot, evFill, evCpy;
    StreamCtx() {
        cudaStreamCreateWithFlags(&s1, cudaStreamNonBlocking);
        cudaStreamCreateWithFlags(&s2, cudaStreamNonBlocking);
        cudaEventCreateWithFlags(&evRoot, cudaEventDisableTiming);
        cudaEventCreateWithFlags(&evFill, cudaEventDisableTiming);
        cudaEventCreateWithFlags(&evCpy,  cudaEventDisableTiming);
    }
};
static StreamCtx g_sc;

// ---------------------------------------------------------------------------
// Fused: histogram destinations + coef[e] = val[e] * dot(cci[e], a).
__global__ void count_kernel(const int* __restrict__ adj0, const int* __restrict__ adj1,
                             const int* __restrict__ inc,
                             const float* __restrict__ val0, const float* __restrict__ cci0,
                             const float* __restrict__ a0,
                             const float* __restrict__ val1, const float* __restrict__ cci1,
                             const float* __restrict__ a1) {
    int t = blockIdx.x * blockDim.x + threadIdx.x;
    if (t >= ET) return;
    int ci;
    if (t < E0) {
        ci = B0 + __ldg(&adj0[E0 + t]);
        const float* c = cci0 + (size_t)t*3;
        g_coef[t] = __ldg(&val0[t]) * (c[0]*a0[0] + c[1]*a0[1] + c[2]*a0[2]);
    } else if (t < E0 + E1) {
        int f = t - E0;
        ci = B1 + __ldg(&adj1[E1 + f]);
        const float* c = cci1 + (size_t)f*3;
        g_coef[E0 + f] = __ldg(&val1[f]) * (c[0]*a1[0] + c[1]*a1[1] + c[2]*a1[2]);
    } else if (t < E0 + E1 + NNZ01) {
        ci = B2 + __ldg(&inc[t - (E0 + E1)]);
    } else {
        ci = B3 + __ldg(&inc[NNZ01 + (t - (E0+E1+NNZ01))]);
    }
    atomicAdd(&g_cnt[ci], 1);
}

// --- 3-pass exclusive scan over g_cnt[NCNT] -> g_offs (non-destructive) ---
__global__ void scan_pass1() {
    __shared__ int wsum[8];
    int tid = threadIdx.x, lane = tid & 31, wid = tid >> 5;
    int base = blockIdx.x * SCAN_BLK + tid * 4;
    int4 v = make_int4(0,0,0,0);
    if (base < NCNT) v = *(const int4*)&g_cnt[base];
    int s = v.x + v.y + v.z + v.w;
    #pragma unroll
    for (int o = 16; o; o >>= 1) s += __shfl_down_sync(0xffffffffu, s, o);
    if (lane == 0) wsum[wid] = s;
    __syncthreads();
    if (tid == 0) {
        int tot = 0;
        #pragma unroll
        for (int i = 0; i < 8; i++) tot += wsum[i];
        g_bsums[blockIdx.x] = tot;
    }
}

__global__ void scan_pass2() {
    __shared__ int sm[512];
    int t = threadIdx.x;
    int v = (t < NB) ? g_bsums[t] : 0;
    sm[t] = v;
    __syncthreads();
    #pragma unroll
    for (int o = 1; o < 512; o <<= 1) {
        int add = (t >= o) ? sm[t - o] : 0;
        __syncthreads();
        sm[t] += add;
        __syncthreads();
    }
    if (t < NB) g_bsums[t] = sm[t] - v;
    if (t == 0) g_offs[NCNT] = ET;
}

__global__ void scan_pass3() {
    __shared__ int woff[8];
    int tid = threadIdx.x, lane = tid & 31, wid = tid >> 5;
    int base = blockIdx.x * SCAN_BLK + tid * 4;
    int4 v = make_int4(0,0,0,0);
    if (base < NCNT) v = *(const int4*)&g_cnt[base];
    int s = v.x + v.y + v.z + v.w;
    int incl = s;
    #pragma unroll
    for (int o = 1; o < 32; o <<= 1) {
        int n = __shfl_up_sync(0xffffffffu, incl, o);
        if (lane >= o) incl += n;
    }
    if (lane == 31) woff[wid] = incl;
    __syncthreads();
    if (tid == 0) {
        int acc = 0;
        #pragma unroll
        for (int i = 0; i < 8; i++) { int t2 = woff[i]; woff[i] = acc; acc += t2; }
    }
    __syncthreads();
    int excl = incl - s + woff[wid] + g_bsums[blockIdx.x];
    if (base < NCNT) {
        g_offs[base]     = excl;
        g_offs[base + 1] = excl + v.x;
        g_offs[base + 2] = excl + v.x + v.y;
        g_offs[base + 3] = excl + v.x + v.y + v.z;
    }
}

// fill: position = offs[ci] + (atomicSub(cnt[ci]) - 1); cnt consumed here.
__global__ void fill_kernel(const int* __restrict__ adj0, const int* __restrict__ adj1,
                            const int* __restrict__ inc, const float* __restrict__ incv) {
    int t = blockIdx.x * blockDim.x + threadIdx.x;
    if (t >= ET) return;
    int ci, src; float coef;
    if (t < E0) {
        ci   = B0 + __ldg(&adj0[E0 + t]);
        src  = __ldg(&adj0[t]);
        coef = g_coef[t];
    } else if (t < E0 + E1) {
        int f = t - E0;
        ci   = B1 + __ldg(&adj1[E1 + f]);
        src  = __ldg(&adj1[f]);
        coef = g_coef[E0 + f];
    } else if (t < E0 + E1 + NNZ01) {
        int f = t - (E0 + E1);
        ci   = B2 + __ldg(&inc[f]);
        src  = __ldg(&inc[NNZ01 + f]);
        coef = __ldg(&incv[f]);
    } else {
        int f = t - (E0 + E1 + NNZ01);
        ci   = B3 + __ldg(&inc[NNZ01 + f]);
        src  = __ldg(&inc[f]);
        coef = __ldg(&incv[f]);
    }
    int pos = g_offs[ci] + (atomicSub(&g_cnt[ci], 1) - 1);
    g_rec[pos] = make_int2(src, __float_as_int(coef));
}

// ---------------------------------------------------------------------------
// Dual GEMM: outA = x @ WA, outB = x @ WB, outputs fp16.
__global__ void __launch_bounds__(128) gemm_dual_kernel(
    const float* __restrict__ x, const float* __restrict__ WA, const float* __restrict__ WB,
    __half* __restrict__ outA, __half* __restrict__ outB, int nrows)
{
    __shared__ float sWA[64*64];
    __shared__ float sWB[64*64];
    __shared__ float sXT[64][36];

    int tid = threadIdx.x;
    for (int i = tid*4; i < 4096; i += 128*4) {
        *(float4*)&sWA[i] = *(const float4*)&WA[i];
        *(float4*)&sWB[i] = *(const float4*)&WB[i];
    }
    int ntiles = (nrows + 31) >> 5;
    int tx = tid & 15;
    int ty = tid >> 4;

    for (int tile = blockIdx.x; tile < ntiles; tile += gridDim.x) {
        int row0 = tile << 5;
        __syncthreads();
        #pragma unroll
        for (int i = 0; i < 4; i++) {
            int q  = tid + i*128;
            int r  = q >> 4;
            int c4 = (q & 15) << 2;
            float4 v = make_float4(0.f,0.f,0.f,0.f);
            if (row0 + r < nrows) v = *(const float4*)&x[(size_t)(row0 + r)*DIM + c4];
            sXT[c4+0][r] = v.x; sXT[c4+1][r] = v.y; sXT[c4+2][r] = v.z; sXT[c4+3][r] = v.w;
        }
        __syncthreads();

        float aA[4][4] = {}; float aB[4][4] = {};
        #pragma unroll
        for (int k = 0; k < 64; k++) {
            float4 xv = *(float4*)&sXT[k][ty*4];
            float4 wa = *(float4*)&sWA[k*64 + tx*4];
            float4 wb = *(float4*)&sWB[k*64 + tx*4];
            float xr[4]  = {xv.x, xv.y, xv.z, xv.w};
            float wac[4] = {wa.x, wa.y, wa.z, wa.w};
            float wbc[4] = {wb.x, wb.y, wb.z, wb.w};
            #pragma unroll
            for (int r = 0; r < 4; r++)
                #pragma unroll
                for (int c = 0; c < 4; c++) {
                    aA[r][c] += xr[r]*wac[c];
                    aB[r][c] += xr[r]*wbc[c];
                }
        }
        #pragma unroll
        for (int r = 0; r < 4; r++) {
            int row = row0 + ty*4 + r;
            if (row < nrows) {
                h4 pa, pb;
                pa.a = __floats2half2_rn(aA[r][0], aA[r][1]);
                pa.b = __floats2half2_rn(aA[r][2], aA[r][3]);
                pb.a = __floats2half2_rn(aB[r][0], aB[r][1]);
                pb.b = __floats2half2_rn(aB[r][2], aB[r][3]);
                *(h4*)&outA[(size_t)row*DIM + tx*4] = pa;
                *(h4*)&outB[(size_t)row*DIM + tx*4] = pb;
            }
        }
    }
}

// ---------------------------------------------------------------------------
// Warp-per-node CSR gather, SHFL-free: all lanes uniform-load each record
// (one sector request, L1 line reused across 16 consecutive records), then
// coalesced half2 gather of the message row. fp32 accumulation.
__device__ __forceinline__ float2 seg_accum(const __half* __restrict__ m,
                                            int s, int e, int lane) {
    float2 acc = make_float2(0.f, 0.f);
    int j = s;
    for (; j + 4 <= e; j += 4) {
        int2 r0 = __ldg(&g_rec[j+0]);
        int2 r1 = __ldg(&g_rec[j+1]);
        int2 r2 = __ldg(&g_rec[j+2]);
        int2 r3 = __ldg(&g_rec[j+3]);
        float2 v0 = __half22float2(*(const __half2*)&m[(size_t)r0.x*DIM + lane*2]);
        float2 v1 = __half22float2(*(const __half2*)&m[(size_t)r1.x*DIM + lane*2]);
        float2 v2 = __half22float2(*(const __half2*)&m[(size_t)r2.x*DIM + lane*2]);
        float2 v3 = __half22float2(*(const __half2*)&m[(size_t)r3.x*DIM + lane*2]);
        float c0 = __int_as_float(r0.y);
        float c1 = __int_as_float(r1.y);
        float c2 = __int_as_float(r2.y);
        float c3 = __int_as_float(r3.y);
        acc.x += c0*v0.x; acc.y += c0*v0.y;
        acc.x += c1*v1.x; acc.y += c1*v1.y;
        acc.x += c2*v2.x; acc.y += c2*v2.y;
        acc.x += c3*v3.x; acc.y += c3*v3.y;
    }
    for (; j < e; j++) {
        int2 r = __ldg(&g_rec[j]);
        float c = __int_as_float(r.y);
        float2 v = __half22float2(*(const __half2*)&m[(size_t)r.x*DIM + lane*2]);
        acc.x += c*v.x; acc.y += c*v.y;
    }
    return acc;
}

__global__ void __launch_bounds__(256) gather_kernel(
    const __half* __restrict__ pm0, const __half* __restrict__ pms,
    const __half* __restrict__ pm1, const __half* __restrict__ pmt,
    float* __restrict__ sum0, float* __restrict__ sum1)
{
    int w    = (blockIdx.x * blockDim.x + threadIdx.x) >> 5;
    int lane = threadIdx.x & 31;
    if (w >= N0 + N1) return;

    const __half *mA, *mB; float* outp; int node, baseA, baseB;
    if (w < N0) { node = w;      mA = pm0; baseA = B0; mB = pms; baseB = B2; outp = sum0; }
    else        { node = w - N0; mA = pm1; baseA = B1; mB = pmt; baseB = B3; outp = sum1; }

    int sA = g_offs[baseA + node], eA = g_offs[baseA + node + 1];
    int sB = g_offs[baseB + node], eB = g_offs[baseB + node + 1];
    float2 a = seg_accum(mA, sA, eA, lane);
    float2 b = seg_accum(mB, sB, eB, lane);
    float2 r;
    r.x = fmaxf(a.x, 0.f) + fmaxf(b.x, 0.f);
    r.y = fmaxf(a.y, 0.f) + fmaxf(b.y, 0.f);
    *(float2*)&outp[(size_t)node*DIM + lane*2] = r;
}

// ---------------------------------------------------------------------------
// Merged epilogue: out = relu(in @ W) for both node families in one launch.
__global__ void __launch_bounds__(256) aggr_kernel(
    const float* __restrict__ in0, const float* __restrict__ W0, float* __restrict__ out0,
    const float* __restrict__ in1, const float* __restrict__ W1, float* __restrict__ out1,
    int tiles0)
{
    __shared__ float sW[64*64];
    __shared__ float sXT[64][68];

    const float *in, *W; float* out; int nrows, tile;
    if ((int)blockIdx.x < tiles0) { in = in0; W = W0; out = out0; nrows = N0; tile = blockIdx.x; }
    else                          { in = in1; W = W1; out = out1; nrows = N1; tile = blockIdx.x - tiles0; }

    int tid = threadIdx.x;
    for (int i = tid*4; i < 4096; i += 256*4)
        *(float4*)&sW[i] = *(const float4*)&W[i];

    int tx = tid & 15;
    int ty = tid >> 4;
    int row0 = tile << 6;

    #pragma unroll
    for (int i = 0; i < 4; i++) {
        int q  = tid + i*256;
        int r  = q >> 4;
        int c4 = (q & 15) << 2;
        float4 v = make_float4(0.f,0.f,0.f,0.f);
        if (row0 + r < nrows)
            v = *(const float4*)&in[(size_t)(row0 + r)*DIM + c4];
        sXT[c4+0][r] = v.x; sXT[c4+1][r] = v.y; sXT[c4+2][r] = v.z; sXT[c4+3][r] = v.w;
    }
    __syncthreads();

    float acc4[4][4] = {};
    #pragma unroll
    for (int k = 0; k < 64; k++) {
        float4 xv = *(float4*)&sXT[k][ty*4];
        float4 w  = *(float4*)&sW[k*64 + tx*4];
        float xr[4] = {xv.x, xv.y, xv.z, xv.w};
        float wc[4] = {w.x, w.y, w.z, w.w};
        #pragma unroll
        for (int r = 0; r < 4; r++)
            #pragma unroll
            for (int c = 0; c < 4; c++)
                acc4[r][c] += xr[r]*wc[c];
    }
    #pragma unroll
    for (int r = 0; r < 4; r++) {
        int row = row0 + ty*4 + r;
        if (row < nrows) {
            *(float4*)&out[(size_t)row*DIM + tx*4] =
                make_float4(fmaxf(acc4[r][0],0.f), fmaxf(acc4[r][1],0.f),
                            fmaxf(acc4[r][2],0.f), fmaxf(acc4[r][3],0.f));
        }
    }
}

// ---------------------------------------------------------------------------
extern "C" void kernel_launch(void* const* d_in, const int* in_sizes, int n_in,
                              void* d_out, int out_size) {
    const float* x0    = (const float*)d_in[0];
    const float* x1    = (const float*)d_in[1];
    const float* x2    = (const float*)d_in[2];
    const float* x3    = (const float*)d_in[3];
    const float* x4    = (const float*)d_in[4];
    const int*   adj0  = (const int*)  d_in[5];
    const float* adj0v = (const float*)d_in[6];
    const int*   adj1  = (const int*)  d_in[7];
    const float* adj1v = (const float*)d_in[8];
    const int*   inc   = (const int*)  d_in[9];
    const float* incv  = (const float*)d_in[10];
    const float* cci0  = (const float*)d_in[11];
    const float* cci1  = (const float*)d_in[12];
    const float* Whbs0 = (const float*)d_in[13];
    const float* a0    = (const float*)d_in[14];
    const float* Whbs1 = (const float*)d_in[15];
    const float* a1    = (const float*)d_in[16];
    const float* Ws    = (const float*)d_in[17];
    const float* Wt    = (const float*)d_in[18];
    const float* Wag0  = (const float*)d_in[19];
    const float* Wag1  = (const float*)d_in[20];
    float* out = (float*)d_out;

    __half *pm; float *psum; int* pcnt;
    cudaGetSymbolAddress((void**)&pm,   g_m);
    cudaGetSymbolAddress((void**)&psum, g_sum);
    cudaGetSymbolAddress((void**)&pcnt, g_cnt);

    __half* pm0 = pm;
    __half* pmt = pm + N0D;
    __half* pm1 = pm + 2*(size_t)N0D;
    __half* pms = pm + 2*(size_t)N0D + N1D;
    float* sum0 = psum;
    float* sum1 = psum + N0D;

    cudaStream_t s1 = g_sc.s1, s2 = g_sc.s2;

    // fork: root event on the capturing stream
    cudaEventRecord(g_sc.evRoot, 0);
    cudaStreamWaitEvent(s1, g_sc.evRoot, 0);
    cudaStreamWaitEvent(s2, g_sc.evRoot, 0);

    // branch s1: binning chain
    cudaMemsetAsync(pcnt, 0, NCNT*sizeof(int), s1);
    count_kernel<<<(ET + 255)/256, 256, 0, s1>>>(adj0, adj1, inc,
                                                 adj0v, cci0, a0, adj1v, cci1, a1);
    scan_pass1<<<NB, 256, 0, s1>>>();
    scan_pass2<<<1, 512, 0, s1>>>();
    scan_pass3<<<NB, 256, 0, s1>>>();
    fill_kernel<<<(ET + 255)/256, 256, 0, s1>>>(adj0, adj1, inc, incv);
    cudaEventRecord(g_sc.evFill, s1);

    // branch s2: passthrough copies (DMA engines)
    size_t off2 = (size_t)(N0 + N1)*DIM;
    size_t off3 = off2 + (size_t)N2*DIM;
    size_t off4 = off3 + (size_t)N3*DIM;
    cudaMemcpyAsync(out + off2, x2, (size_t)N2*DIM*sizeof(float), cudaMemcpyDeviceToDevice, s2);
    cudaMemcpyAsync(out + off3, x3, (size_t)N3*DIM*sizeof(float), cudaMemcpyDeviceToDevice, s2);
    cudaMemcpyAsync(out + off4, x4, (size_t)N4*DIM*sizeof(float), cudaMemcpyDeviceToDevice, s2);
    cudaEventRecord(g_sc.evCpy, s2);

    // branch 0: dense projections
    gemm_dual_kernel<<<740, 128>>>(x0, Whbs0, Wt, pm0, pmt, N0);
    gemm_dual_kernel<<<740, 128>>>(x1, Whbs1, Ws, pm1, pms, N1);

    // join: gather needs fill + both GEMMs
    cudaStreamWaitEvent(0, g_sc.evFill, 0);
    gather_kernel<<<((N0 + N1)*32 + 255)/256, 256>>>(pm0, pms, pm1, pmt, sum0, sum1);

    // epilogue GEMMs straight into d_out
    int tiles0 = (N0 + 63)/64, tiles1 = (N1 + 63)/64;
    aggr_kernel<<<tiles0 + tiles1, 256>>>(sum0, Wag0, out,
                                          sum1, Wag1, out + (size_t)N0*DIM, tiles0);

    // join copies back into the capturing stream before return
    cudaStreamWaitEvent(0, g_sc.evCpy, 0);
}